// round 13
// baseline (speedup 1.0000x reference)
#include <cuda_runtime.h>
#include <stdint.h>

// Diagnostic restructure: k_power moved to the 4th launch slot (the one ncu
// captures) by merging k_zero into k_permute and k_fill into k_power's head.

// Problem constants (fixed shapes)
#define NN   10000       // nodes
#define BB   4           // batch
#define FIN  16          // input features
#define TT   8           // time steps
#define CCH  32          // cheb channels
#define CTM  64          // time channels
#define MAXE 160000      // edges
#define ITERS 64         // power iterations
#define CSZ  8           // cluster size (CTAs) for k_power
#define NPC  1250        // nodes per CTA (NN / CSZ)
#define ECAP 24000       // per-CTA smem edge cache capacity (mean 20000)
#define TOTX (NN*512)    // Tx element count = N * F(16) * TB(32)

// ---------------- scratch (device globals; no allocation) ----------------
__device__ __align__(16) float g_Tx0[TOTX];
__device__ __align__(16) float g_Tx1[TOTX];
__device__ __align__(16) float g_cheb[NN*1024];   // [n][tb(32)][c(32)]
__device__ int   g_indeg[NN];
__device__ int   g_rowptr[NN+1];
__device__ int   g_cursor[NN];
__device__ int   g_col[MAXE];
__device__ __align__(16) float g_u0[NN];
__device__ __align__(16) float g_u1[NN];
__device__ float g_S[ITERS+1];
__device__ float g_lmax;
__device__ float g_diag[NN];

// ---------------- packed f32x2 helpers (sm_100a) -------------------------
__device__ __forceinline__ unsigned long long pk2(float a, float b) {
    unsigned long long r;
    asm("mov.b64 %0, {%1, %2};" : "=l"(r) : "f"(a), "f"(b));
    return r;
}
__device__ __forceinline__ void fma2(unsigned long long& d, unsigned long long a, unsigned long long b) {
    asm("fma.rn.f32x2 %0, %1, %2, %0;" : "+l"(d) : "l"(a), "l"(b));
}
__device__ __forceinline__ float2 upk2(unsigned long long v) {
    float2 f;
    asm("mov.b64 {%0, %1}, %2;" : "=f"(f.x), "=f"(f.y) : "l"(v));
    return f;
}

// ---------------- permute + zero (launch 1) ------------------------------
// Permute X(B,N,F,T) -> Tx0 = (F,B,N,T) flat: the reference's reshape makes
// graph row n2 = flat[(n2*512):(n2*512+512)] of the (F,B,N,T) array.
// Piggybacks the g_indeg / g_S zeroing (prerequisite for k_hist / k_power).
__global__ void k_permute(const float* __restrict__ X) {
    int i = blockIdx.x * blockDim.x + threadIdx.x;   // [0, 640000)
    if (i < NN) g_indeg[i] = 0;
    if (i <= ITERS) g_S[i] = 0.0f;
    if (i >= NN * BB * FIN) return;
    int f = i / (BB * NN);
    int r = i - f * (BB * NN);
    int b = r / NN;
    int n = r - b * NN;
    const float4* src = reinterpret_cast<const float4*>(X + ((size_t)((b * NN + n) * FIN + f)) * TT);
    float4* dst = reinterpret_cast<float4*>(g_Tx0 + (size_t)i * TT);
    dst[0] = src[0];
    dst[1] = src[1];
}

__global__ void k_hist(const int* __restrict__ dst, int E) {
    int e = blockIdx.x * blockDim.x + threadIdx.x;
    if (e < E) atomicAdd(&g_indeg[dst[e]], 1);
}

__global__ void k_scan() {   // 1 block, 1024 threads
    __shared__ int ps[1024];
    const int CH = 10;       // 1024*10 >= NN
    int t = threadIdx.x;
    int base = t * CH;
    int sum = 0;
#pragma unroll
    for (int i = 0; i < CH; i++) { int idx = base + i; if (idx < NN) sum += g_indeg[idx]; }
    ps[t] = sum; __syncthreads();
    for (int off = 1; off < 1024; off <<= 1) {
        int v = ps[t];
        int a = (t >= off) ? ps[t - off] : 0;
        __syncthreads();
        ps[t] = v + a;
        __syncthreads();
    }
    int run = (t == 0) ? 0 : ps[t - 1];
#pragma unroll
    for (int i = 0; i < CH; i++) {
        int idx = base + i;
        if (idx < NN) { g_rowptr[idx] = run; g_cursor[idx] = run; run += g_indeg[idx]; }
    }
    if (t == 1023) g_rowptr[NN] = ps[1023];
}

// ---------------- power iteration (launch 4 — profiled) ------------------
// Head: CSR fill (moved from k_fill), then threadfence + cluster barrier.
// Body: R12's validated logic — per-CTA smem edge cache, full 40KB iterate
// staged from L2 each iteration, LDS gathers, smem-tree norm reduce,
// global-atomic S accumulation, HW cluster barrier per iteration.
// Per-node arithmetic identical to all passing rounds:
//   iter 1: w = fl(deg*C0) - chain_deg(C0)   (null-space rounding residue)
//   iter k: acc = (deg*cur[n] - sum cur[col]) * (1/sqrt(S[k-1]))
__global__ void __cluster_dims__(CSZ, 1, 1) __launch_bounds__(1024, 1)
k_power(const int* __restrict__ esrc, const int* __restrict__ edst, int E) {
    extern __shared__ __align__(16) float dyn[];   // [NN] vector + [ECAP] edges
    float* sm = dyn;
    int*   se = reinterpret_cast<int*>(dyn + NN);
    __shared__ float red[1024];
    uint32_t rank;
    asm("mov.u32 %0, %%cluster_ctarank;" : "=r"(rank));
    int tid = threadIdx.x;
    const float C0 = 0.01f;                 // 1/sqrt(10000) rounded to f32

    // ---- fill phase (was k_fill) ----
    int GT = (int)rank * 1024 + tid;        // 0..8191
    for (int e = GT; e < E; e += CSZ * 1024) {
        int d = edst[e];
        int p = atomicAdd(&g_cursor[d], 1);
        g_col[p] = esrc[e];
    }
    __threadfence();
    asm volatile("barrier.cluster.arrive.aligned;" ::: "memory");
    asm volatile("barrier.cluster.wait.aligned;" ::: "memory");

    // ---- edge-cache load ----
    int base  = (int)rank * NPC;
    int ebase = g_rowptr[base];
    int ecnt  = g_rowptr[base + NPC] - ebase;
    bool fastE = (ecnt <= ECAP);
    for (int i = tid; i < ecnt && i < ECAP; i += 1024)
        se[i] = __ldcg(&g_col[ebase + i]);

    int n0 = base + tid;                    // always valid (tid < 1024 < 1250)
    int n1 = base + 1024 + tid;
    bool v1 = (tid < NPC - 1024);           // tid < 226
    int l00 = g_rowptr[n0] - ebase;
    int m0  = g_rowptr[n0 + 1] - (l00 + ebase);
    int l01 = 0, m1 = 0;
    if (v1) { l01 = g_rowptr[n1] - ebase; m1 = g_rowptr[n1 + 1] - (l01 + ebase); }
    float deg0 = (float)m0, deg1 = (float)m1;
    __syncthreads();

    float* cur = g_u0;   // read buffer for iter k (k>=2)
    float* nxt = g_u1;   // write buffer for iter k
    for (int k = 1; k <= ITERS; k++) {
        float part = 0.0f;
        if (k == 1) {
            {
                float av = 0.0f;
                for (int j = 0; j < m0; j++) av = __fadd_rn(av, C0);
                float w = __fsub_rn(__fmul_rn(deg0, C0), av);
                nxt[n0] = w;
                part += w * w;
            }
            if (v1) {
                float av = 0.0f;
                for (int j = 0; j < m1; j++) av = __fadd_rn(av, C0);
                float w = __fsub_rn(__fmul_rn(deg1, C0), av);
                nxt[n1] = w;
                part += w * w;
            }
        } else {
            // stage full iterate from L2 (written by all CTAs last iter)
            const float4* c4 = reinterpret_cast<const float4*>(cur);
            float4* s4 = reinterpret_cast<float4*>(sm);
            for (int i = tid; i < NN / 4; i += 1024)
                s4[i] = __ldcg(c4 + i);
            __syncthreads();

            float inv = 1.0f / sqrtf(__ldcg(&g_S[k - 1]));
            {
                float acc = deg0 * sm[n0];
                if (fastE) {
#pragma unroll 4
                    for (int j = 0; j < m0; j++) acc -= sm[se[l00 + j]];
                } else {
                    for (int j = 0; j < m0; j++) acc -= sm[__ldcg(&g_col[ebase + l00 + j])];
                }
                acc *= inv;
                nxt[n0] = acc;
                part += acc * acc;
            }
            if (v1) {
                float acc = deg1 * sm[n1];
                if (fastE) {
#pragma unroll 4
                    for (int j = 0; j < m1; j++) acc -= sm[se[l01 + j]];
                } else {
                    for (int j = 0; j < m1; j++) acc -= sm[__ldcg(&g_col[ebase + l01 + j])];
                }
                acc *= inv;
                nxt[n1] = acc;
                part += acc * acc;
            }
        }
        red[tid] = part; __syncthreads();
        for (int s = 512; s > 0; s >>= 1) {
            if (tid < s) red[tid] += red[tid + s];
            __syncthreads();
        }
        if (tid == 0) atomicAdd(&g_S[k], red[0]);
        __threadfence();
        asm volatile("barrier.cluster.arrive.aligned;" ::: "memory");
        asm volatile("barrier.cluster.wait.aligned;" ::: "memory");
        float* tmp = cur; cur = nxt; nxt = tmp;
    }
    float lm = sqrtf(__ldcg(&g_S[ITERS]));
    if (rank == 0 && tid == 0) g_lmax = lm;
    for (int i = (int)rank * 1024 + tid; i < NN; i += CSZ * 1024)
        g_diag[i] = 2.0f * (float)g_indeg[i] / lm - 1.0f;
}

// ---------------- lhat1: Tx1 = diag*Tx0 - off * A^T Tx0 -----------------
__global__ void k_lhat1() {
    int n = blockIdx.x;
    int t = threadIdx.x;   // 0..127, float4 chunk of the 512-float row
    const float4* x0 = reinterpret_cast<const float4*>(g_Tx0);
    float4 acc = make_float4(0.f, 0.f, 0.f, 0.f);
    int e0 = g_rowptr[n], e1 = g_rowptr[n + 1];
    for (int j = e0; j < e1; j++) {
        int s = g_col[j];
        float4 v = x0[s * 128 + t];
        acc.x += v.x; acc.y += v.y; acc.z += v.z; acc.w += v.w;
    }
    float off = 2.0f / g_lmax;
    float dg  = g_diag[n];
    float4 xx = x0[n * 128 + t];
    float4 o;
    o.x = dg * xx.x - off * acc.x;
    o.y = dg * xx.y - off * acc.y;
    o.z = dg * xx.z - off * acc.z;
    o.w = dg * xx.w - off * acc.w;
    reinterpret_cast<float4*>(g_Tx1)[n * 128 + t] = o;
}

// ------- lhat2 (Tx2 = 2*lhat(Tx1)-Tx0) fused with Cheb GEMM + ReLU ------
// Rows f-major: element (f2, tb) at local index f2*32 + tb.
__global__ void k_lhat2cheb(const float* __restrict__ chebW, const float* __restrict__ chebB) {
    __shared__ __align__(16) float sT[1536];   // Tx0,Tx1,Tx2 rows of this node
    __shared__ float sW[1536];                 // cheb_W (3,16,32)
    __shared__ float sB[CCH];
    int n = blockIdx.x;
    int t = threadIdx.x;   // 128 threads
    for (int i = t; i < 1536; i += 128) sW[i] = chebW[i];
    if (t < CCH) sB[t] = chebB[t];

    const float4* x0 = reinterpret_cast<const float4*>(g_Tx0);
    const float4* x1 = reinterpret_cast<const float4*>(g_Tx1);
    float4 acc = make_float4(0.f, 0.f, 0.f, 0.f);
    int e0 = g_rowptr[n], e1 = g_rowptr[n + 1];
    for (int j = e0; j < e1; j++) {
        int s = g_col[j];
        float4 v = x1[s * 128 + t];
        acc.x += v.x; acc.y += v.y; acc.z += v.z; acc.w += v.w;
    }
    float off = 2.0f / g_lmax;
    float dg  = g_diag[n];
    float4 a1 = x1[n * 128 + t];
    float4 a0 = x0[n * 128 + t];
    float4 t2;
    t2.x = 2.f * (dg * a1.x - off * acc.x) - a0.x;
    t2.y = 2.f * (dg * a1.y - off * acc.y) - a0.y;
    t2.z = 2.f * (dg * a1.z - off * acc.z) - a0.z;
    t2.w = 2.f * (dg * a1.w - off * acc.w) - a0.w;
    reinterpret_cast<float4*>(sT)[t]       = a0;   // Tx0 row (f-major)
    reinterpret_cast<float4*>(sT)[128 + t] = a1;   // Tx1 row
    reinterpret_cast<float4*>(sT)[256 + t] = t2;   // Tx2 row
    __syncthreads();

    // out[tb][c] = relu(b_c + sum_k sum_f Txk[f][tb]*W[k][f][c])
    int tb = t >> 2;
    int c0 = (t & 3) << 3;   // 8 channels per thread
    float y[8];
#pragma unroll
    for (int i = 0; i < 8; i++) y[i] = 0.f;
#pragma unroll
    for (int k = 0; k < 3; k++) {
        const float* xr = sT + k * 512 + tb;       // element f at xr[f*32]
        const float* wk = sW + k * 512;
#pragma unroll
        for (int f = 0; f < FIN; f++) {
            float xv = xr[f * 32];
            const float* wr = wk + f * 32 + c0;
#pragma unroll
            for (int i = 0; i < 8; i++) y[i] += xv * wr[i];
        }
    }
    float* outp = g_cheb + n * 1024 + tb * 32 + c0;
#pragma unroll
    for (int i = 0; i < 8; i++) outp[i] = fmaxf(y[i] + sB[c0 + i], 0.f);
}

// ------- final: time conv + residual + ReLU + LayerNorm + write ---------
// per (b,n) unit: Y(64x8) = A(64x112) * Z(112x8) + bias ; relu ; LN over 64
// GEMM uses packed fma.rn.f32x2 (identical rounding to scalar FFMA chain).
__global__ void k_final(const float* __restrict__ X,
                        const float* __restrict__ timeW, const float* __restrict__ timeB,
                        const float* __restrict__ resW,  const float* __restrict__ resB,
                        const float* __restrict__ gamma, const float* __restrict__ beta,
                        float* __restrict__ out) {
    __shared__ float As[112 * 64];                   // transposed: As[kk*64+co]
    __shared__ __align__(16) float Zs[4][896];       // per-group Z (112x8)
    __shared__ float sBias[64], sG[64], sBt[64];
    __shared__ float redS[4][2][8], redQ[4][2][8];
    int tid = threadIdx.x;

    for (int i = tid; i < 7168; i += 256) {
        int kk = i >> 6, co = i & 63;
        float w;
        if (kk < 96) { int ci = kk / 3, dt = kk - ci * 3; w = timeW[co * 96 + ci * 3 + dt]; }
        else         { w = resW[co * 16 + (kk - 96)]; }
        As[i] = w;
    }
    if (tid < 64) { sBias[tid] = timeB[tid] + resB[tid]; sG[tid] = gamma[tid]; sBt[tid] = beta[tid]; }
    __syncthreads();

    int g = tid >> 6, co = tid & 63;
    int lane = tid & 31, wsub = (tid >> 5) & 1;

    for (int round = 0; round < 8; round++) {
        int unit = blockIdx.x * 32 + round * 4 + g;   // 0..39999
        int b = unit / NN, n = unit - b * NN;

        // build Z: kk<96 -> time-conv patch (ci,dt), kk>=96 -> residual X
        const float* cbase = g_cheb + n * 1024 + b * 256;       // [tau*32+ci]
        const float* xbase = X + (size_t)(b * NN + n) * 128;    // [f*8+t]
        float* Z = Zs[g];
        for (int i = co; i < 896; i += 64) {
            int kk = i >> 3, t = i & 7;
            float v;
            if (kk < 96) {
                int ci = kk / 3, dt = kk - ci * 3;
                int tau = t + dt - 1;
                v = (tau >= 0 && tau < TT) ? cbase[tau * 32 + ci] : 0.f;
            } else {
                v = xbase[(kk - 96) * 8 + t];
            }
            Z[i] = v;
        }
        __syncthreads();

        float bco = sBias[co];
        unsigned long long y01 = pk2(bco, bco);
        unsigned long long y23 = pk2(bco, bco);
        unsigned long long y45 = pk2(bco, bco);
        unsigned long long y67 = pk2(bco, bco);
        const float4* Z4 = reinterpret_cast<const float4*>(Z);
        const float*  Ap = As + co;
#pragma unroll 4
        for (int kk = 0; kk < 112; kk++) {
            float a = Ap[kk * 64];
            unsigned long long aa = pk2(a, a);
            float4 z0 = Z4[kk * 2];
            float4 z1 = Z4[kk * 2 + 1];
            fma2(y01, aa, pk2(z0.x, z0.y));
            fma2(y23, aa, pk2(z0.z, z0.w));
            fma2(y45, aa, pk2(z1.x, z1.y));
            fma2(y67, aa, pk2(z1.z, z1.w));
        }
        float y[8];
        { float2 p = upk2(y01); y[0] = p.x; y[1] = p.y; }
        { float2 p = upk2(y23); y[2] = p.x; y[3] = p.y; }
        { float2 p = upk2(y45); y[4] = p.x; y[5] = p.y; }
        { float2 p = upk2(y67); y[6] = p.x; y[7] = p.y; }
#pragma unroll
        for (int t = 0; t < 8; t++) y[t] = fmaxf(y[t], 0.f);

        // LayerNorm over 64 channels — two-pass (matches jnp.var semantics)
        float s[8];
#pragma unroll
        for (int t = 0; t < 8; t++) s[t] = y[t];
#pragma unroll
        for (int off = 16; off > 0; off >>= 1) {
#pragma unroll
            for (int t = 0; t < 8; t++) s[t] += __shfl_xor_sync(0xffffffffu, s[t], off);
        }
        if (lane == 0) {
#pragma unroll
            for (int t = 0; t < 8; t++) redS[g][wsub][t] = s[t];
        }
        __syncthreads();

        float mu[8], q[8];
#pragma unroll
        for (int t = 0; t < 8; t++) {
            mu[t] = (redS[g][0][t] + redS[g][1][t]) * (1.f / 64.f);
            float d = y[t] - mu[t];
            q[t] = d * d;
        }
#pragma unroll
        for (int off = 16; off > 0; off >>= 1) {
#pragma unroll
            for (int t = 0; t < 8; t++) q[t] += __shfl_xor_sync(0xffffffffu, q[t], off);
        }
        if (lane == 0) {
#pragma unroll
            for (int t = 0; t < 8; t++) redQ[g][wsub][t] = q[t];
        }
        __syncthreads();

        float ov[8];
#pragma unroll
        for (int t = 0; t < 8; t++) {
            float var = (redQ[g][0][t] + redQ[g][1][t]) * (1.f / 64.f);
            float inv = rsqrtf(var + 1e-5f);
            ov[t] = (y[t] - mu[t]) * inv * sG[co] + sBt[co];
        }
        float4* op = reinterpret_cast<float4*>(out + ((size_t)unit * 64 + co) * 8);
        op[0] = make_float4(ov[0], ov[1], ov[2], ov[3]);
        op[1] = make_float4(ov[4], ov[5], ov[6], ov[7]);
    }
}

// ---------------- launch ----------------
extern "C" void kernel_launch(void* const* d_in, const int* in_sizes, int n_in,
                              void* d_out, int out_size) {
    const float* X     = (const float*)d_in[0];
    const int*   ei    = (const int*)  d_in[1];
    const float* chebW = (const float*)d_in[2];
    const float* chebB = (const float*)d_in[3];
    const float* timeW = (const float*)d_in[4];
    const float* timeB = (const float*)d_in[5];
    const float* resW  = (const float*)d_in[6];
    const float* resB  = (const float*)d_in[7];
    const float* gam   = (const float*)d_in[8];
    const float* bet   = (const float*)d_in[9];
    float* out = (float*)d_out;

    int E = in_sizes[1] / 2;
    const int* src = ei;
    const int* dst = ei + E;
    int EB = (E + 255) / 256;

    const int PSMEM = (NN + ECAP) * (int)sizeof(float);   // 136000 B
    static int smem_set = 0;
    if (!smem_set) {
        cudaFuncSetAttribute(k_power, cudaFuncAttributeMaxDynamicSharedMemorySize, PSMEM);
        smem_set = 1;
    }

    k_permute<<<(NN * BB * FIN + 255) / 256, 256>>>(X);       // 1 (+zero)
    k_hist<<<EB, 256>>>(dst, E);                              // 2
    k_scan<<<1, 1024>>>();                                    // 3
    k_power<<<CSZ, 1024, PSMEM>>>(src, dst, E);               // 4  <- profiled
    k_lhat1<<<NN, 128>>>();                                   // 5
    k_lhat2cheb<<<NN, 128>>>(chebW, chebB);                   // 6
    k_final<<<1250, 256>>>(X, timeW, timeB, resW, resB, gam, bet, out);  // 7
}

// round 14
// speedup vs baseline: 1.0442x; 1.0442x over previous
#include <cuda_runtime.h>
#include <stdint.h>

// R14: k_power loop de-serialized — per-CTA local norm from staged vector
// (no cross-CTA atomic/S exchange, no 10-level tree), shuffle reductions.
// All vector-element arithmetic identical to R13. k_power stays in the
// profiled (4th) launch slot.

// Problem constants (fixed shapes)
#define NN   10000       // nodes
#define BB   4           // batch
#define FIN  16          // input features
#define TT   8           // time steps
#define CCH  32          // cheb channels
#define CTM  64          // time channels
#define MAXE 160000      // edges
#define ITERS 64         // power iterations
#define CSZ  8           // cluster size (CTAs) for k_power
#define NPC  1250        // nodes per CTA (NN / CSZ)
#define ECAP 24000       // per-CTA smem edge cache capacity (mean 20000)
#define TOTX (NN*512)    // Tx element count = N * F(16) * TB(32)

// ---------------- scratch (device globals; no allocation) ----------------
__device__ __align__(16) float g_Tx0[TOTX];
__device__ __align__(16) float g_Tx1[TOTX];
__device__ __align__(16) float g_cheb[NN*1024];   // [n][tb(32)][c(32)]
__device__ int   g_indeg[NN];
__device__ int   g_rowptr[NN+1];
__device__ int   g_cursor[NN];
__device__ int   g_col[MAXE];
__device__ __align__(16) float g_u0[NN];
__device__ __align__(16) float g_u1[NN];
__device__ float g_lmax;
__device__ float g_diag[NN];

// ---------------- packed f32x2 helpers (sm_100a) -------------------------
__device__ __forceinline__ unsigned long long pk2(float a, float b) {
    unsigned long long r;
    asm("mov.b64 %0, {%1, %2};" : "=l"(r) : "f"(a), "f"(b));
    return r;
}
__device__ __forceinline__ void fma2(unsigned long long& d, unsigned long long a, unsigned long long b) {
    asm("fma.rn.f32x2 %0, %1, %2, %0;" : "+l"(d) : "l"(a), "l"(b));
}
__device__ __forceinline__ float2 upk2(unsigned long long v) {
    float2 f;
    asm("mov.b64 {%0, %1}, %2;" : "=f"(f.x), "=f"(f.y) : "l"(v));
    return f;
}

// ---------------- permute + zero (launch 1) ------------------------------
__global__ void k_permute(const float* __restrict__ X) {
    int i = blockIdx.x * blockDim.x + threadIdx.x;   // [0, 640000)
    if (i < NN) g_indeg[i] = 0;
    if (i >= NN * BB * FIN) return;
    int f = i / (BB * NN);
    int r = i - f * (BB * NN);
    int b = r / NN;
    int n = r - b * NN;
    const float4* src = reinterpret_cast<const float4*>(X + ((size_t)((b * NN + n) * FIN + f)) * TT);
    float4* dst = reinterpret_cast<float4*>(g_Tx0 + (size_t)i * TT);
    dst[0] = src[0];
    dst[1] = src[1];
}

__global__ void k_hist(const int* __restrict__ dst, int E) {
    int e = blockIdx.x * blockDim.x + threadIdx.x;
    if (e < E) atomicAdd(&g_indeg[dst[e]], 1);
}

__global__ void k_scan() {   // 1 block, 1024 threads
    __shared__ int ps[1024];
    const int CH = 10;       // 1024*10 >= NN
    int t = threadIdx.x;
    int base = t * CH;
    int sum = 0;
#pragma unroll
    for (int i = 0; i < CH; i++) { int idx = base + i; if (idx < NN) sum += g_indeg[idx]; }
    ps[t] = sum; __syncthreads();
    for (int off = 1; off < 1024; off <<= 1) {
        int v = ps[t];
        int a = (t >= off) ? ps[t - off] : 0;
        __syncthreads();
        ps[t] = v + a;
        __syncthreads();
    }
    int run = (t == 0) ? 0 : ps[t - 1];
#pragma unroll
    for (int i = 0; i < CH; i++) {
        int idx = base + i;
        if (idx < NN) { g_rowptr[idx] = run; g_cursor[idx] = run; run += g_indeg[idx]; }
    }
    if (t == 1023) g_rowptr[NN] = ps[1023];
}

// ---------------- power iteration (launch 4 — profiled) ------------------
// Head: CSR fill, fence, cluster barrier, per-CTA smem edge cache.
// Loop (k>=2): stage full iterate from L2 into smem WITH fused sum-of-
// squares -> per-CTA local S[k-1] via shuffle reduce (identical bits in
// every CTA: same order) -> gather (LDS) -> normalize -> coalesced global
// write -> fence -> HW cluster barrier. No cross-CTA norm exchange.
// Vector-element arithmetic identical to R13:
//   iter 1: w = fl(deg*C0) - chain_deg(C0)   (null-space rounding residue)
//   iter k: acc = (deg*cur[n] - sum cur[col]) * (1/sqrt(S[k-1]))
__global__ void __cluster_dims__(CSZ, 1, 1) __launch_bounds__(1024, 1)
k_power(const int* __restrict__ esrc, const int* __restrict__ edst, int E) {
    extern __shared__ __align__(16) float dyn[];   // [NN] vector + [ECAP] edges
    float* sm = dyn;
    int*   se = reinterpret_cast<int*>(dyn + NN);
    __shared__ float red[33];                      // 32 warp partials + bcast
    uint32_t rank;
    asm("mov.u32 %0, %%cluster_ctarank;" : "=r"(rank));
    int tid = threadIdx.x;
    int lane = tid & 31, warp = tid >> 5;
    const float C0 = 0.01f;                 // 1/sqrt(10000) rounded to f32

    // ---- fill phase ----
    int GT = (int)rank * 1024 + tid;        // 0..8191
    for (int e = GT; e < E; e += CSZ * 1024) {
        int d = edst[e];
        int p = atomicAdd(&g_cursor[d], 1);
        g_col[p] = esrc[e];
    }
    __threadfence();
    asm volatile("barrier.cluster.arrive.aligned;" ::: "memory");
    asm volatile("barrier.cluster.wait.aligned;" ::: "memory");

    // ---- edge-cache load ----
    int base  = (int)rank * NPC;
    int ebase = g_rowptr[base];
    int ecnt  = g_rowptr[base + NPC] - ebase;
    bool fastE = (ecnt <= ECAP);
    for (int i = tid; i < ecnt && i < ECAP; i += 1024)
        se[i] = __ldcg(&g_col[ebase + i]);

    int n0 = base + tid;                    // always valid (tid < 1024 < 1250)
    int n1 = base + 1024 + tid;
    bool v1 = (tid < NPC - 1024);           // tid < 226
    int l00 = g_rowptr[n0] - ebase;
    int m0  = g_rowptr[n0 + 1] - (l00 + ebase);
    int l01 = 0, m1 = 0;
    if (v1) { l01 = g_rowptr[n1] - ebase; m1 = g_rowptr[n1 + 1] - (l01 + ebase); }
    float deg0 = (float)m0, deg1 = (float)m1;
    __syncthreads();

    float* cur = g_u0;   // read buffer for iter k (k>=2)
    float* nxt = g_u1;   // write buffer for iter k
    for (int k = 1; k <= ITERS; k++) {
        if (k == 1) {
            {
                float av = 0.0f;
                for (int j = 0; j < m0; j++) av = __fadd_rn(av, C0);
                float w = __fsub_rn(__fmul_rn(deg0, C0), av);
                nxt[n0] = w;
            }
            if (v1) {
                float av = 0.0f;
                for (int j = 0; j < m1; j++) av = __fadd_rn(av, C0);
                float w = __fsub_rn(__fmul_rn(deg1, C0), av);
                nxt[n1] = w;
            }
        } else {
            // stage full iterate from L2 with fused sum-of-squares
            const float4* c4 = reinterpret_cast<const float4*>(cur);
            float4* s4 = reinterpret_cast<float4*>(sm);
            float ss = 0.0f;
            for (int i = tid; i < NN / 4; i += 1024) {
                float4 f = __ldcg(c4 + i);
                s4[i] = f;
                ss += f.x * f.x + f.y * f.y + f.z * f.z + f.w * f.w;
            }
#pragma unroll
            for (int off = 16; off > 0; off >>= 1)
                ss += __shfl_xor_sync(0xffffffffu, ss, off);
            if (lane == 0) red[warp] = ss;
            __syncthreads();          // covers staging + red[]
            if (warp == 0) {
                float v = red[lane];  // exactly 32 warps
#pragma unroll
                for (int off = 16; off > 0; off >>= 1)
                    v += __shfl_xor_sync(0xffffffffu, v, off);
                if (lane == 0) red[32] = v;
            }
            __syncthreads();
            float inv = 1.0f / sqrtf(red[32]);

            {
                float acc = deg0 * sm[n0];
                if (fastE) {
#pragma unroll 4
                    for (int j = 0; j < m0; j++) acc -= sm[se[l00 + j]];
                } else {
                    for (int j = 0; j < m0; j++) acc -= sm[__ldcg(&g_col[ebase + l00 + j])];
                }
                acc *= inv;
                nxt[n0] = acc;
            }
            if (v1) {
                float acc = deg1 * sm[n1];
                if (fastE) {
#pragma unroll 4
                    for (int j = 0; j < m1; j++) acc -= sm[se[l01 + j]];
                } else {
                    for (int j = 0; j < m1; j++) acc -= sm[__ldcg(&g_col[ebase + l01 + j])];
                }
                acc *= inv;
                nxt[n1] = acc;
            }
        }
        __threadfence();
        asm volatile("barrier.cluster.arrive.aligned;" ::: "memory");
        asm volatile("barrier.cluster.wait.aligned;" ::: "memory");
        float* tmp = cur; cur = nxt; nxt = tmp;
    }

    // final norm ||u_64|| -> lambda_max (per-CTA redundant, deterministic)
    {
        const float4* c4 = reinterpret_cast<const float4*>(cur);
        float ss = 0.0f;
        for (int i = tid; i < NN / 4; i += 1024) {
            float4 f = __ldcg(c4 + i);
            ss += f.x * f.x + f.y * f.y + f.z * f.z + f.w * f.w;
        }
#pragma unroll
        for (int off = 16; off > 0; off >>= 1)
            ss += __shfl_xor_sync(0xffffffffu, ss, off);
        if (lane == 0) red[warp] = ss;
        __syncthreads();
        if (warp == 0) {
            float v = red[lane];
#pragma unroll
            for (int off = 16; off > 0; off >>= 1)
                v += __shfl_xor_sync(0xffffffffu, v, off);
            if (lane == 0) red[32] = v;
        }
        __syncthreads();
        float lm = sqrtf(red[32]);
        if (rank == 0 && tid == 0) g_lmax = lm;
        for (int i = (int)rank * 1024 + tid; i < NN; i += CSZ * 1024)
            g_diag[i] = 2.0f * (float)g_indeg[i] / lm - 1.0f;
    }
}

// ---------------- lhat1: Tx1 = diag*Tx0 - off * A^T Tx0 -----------------
__global__ void k_lhat1() {
    int n = blockIdx.x;
    int t = threadIdx.x;   // 0..127, float4 chunk of the 512-float row
    const float4* x0 = reinterpret_cast<const float4*>(g_Tx0);
    float4 acc = make_float4(0.f, 0.f, 0.f, 0.f);
    int e0 = g_rowptr[n], e1 = g_rowptr[n + 1];
    for (int j = e0; j < e1; j++) {
        int s = g_col[j];
        float4 v = x0[s * 128 + t];
        acc.x += v.x; acc.y += v.y; acc.z += v.z; acc.w += v.w;
    }
    float off = 2.0f / g_lmax;
    float dg  = g_diag[n];
    float4 xx = x0[n * 128 + t];
    float4 o;
    o.x = dg * xx.x - off * acc.x;
    o.y = dg * xx.y - off * acc.y;
    o.z = dg * xx.z - off * acc.z;
    o.w = dg * xx.w - off * acc.w;
    reinterpret_cast<float4*>(g_Tx1)[n * 128 + t] = o;
}

// ------- lhat2 (Tx2 = 2*lhat(Tx1)-Tx0) fused with Cheb GEMM + ReLU ------
// Rows f-major: element (f2, tb) at local index f2*32 + tb.
__global__ void k_lhat2cheb(const float* __restrict__ chebW, const float* __restrict__ chebB) {
    __shared__ __align__(16) float sT[1536];   // Tx0,Tx1,Tx2 rows of this node
    __shared__ float sW[1536];                 // cheb_W (3,16,32)
    __shared__ float sB[CCH];
    int n = blockIdx.x;
    int t = threadIdx.x;   // 128 threads
    for (int i = t; i < 1536; i += 128) sW[i] = chebW[i];
    if (t < CCH) sB[t] = chebB[t];

    const float4* x0 = reinterpret_cast<const float4*>(g_Tx0);
    const float4* x1 = reinterpret_cast<const float4*>(g_Tx1);
    float4 acc = make_float4(0.f, 0.f, 0.f, 0.f);
    int e0 = g_rowptr[n], e1 = g_rowptr[n + 1];
    for (int j = e0; j < e1; j++) {
        int s = g_col[j];
        float4 v = x1[s * 128 + t];
        acc.x += v.x; acc.y += v.y; acc.z += v.z; acc.w += v.w;
    }
    float off = 2.0f / g_lmax;
    float dg  = g_diag[n];
    float4 a1 = x1[n * 128 + t];
    float4 a0 = x0[n * 128 + t];
    float4 t2;
    t2.x = 2.f * (dg * a1.x - off * acc.x) - a0.x;
    t2.y = 2.f * (dg * a1.y - off * acc.y) - a0.y;
    t2.z = 2.f * (dg * a1.z - off * acc.z) - a0.z;
    t2.w = 2.f * (dg * a1.w - off * acc.w) - a0.w;
    reinterpret_cast<float4*>(sT)[t]       = a0;   // Tx0 row (f-major)
    reinterpret_cast<float4*>(sT)[128 + t] = a1;   // Tx1 row
    reinterpret_cast<float4*>(sT)[256 + t] = t2;   // Tx2 row
    __syncthreads();

    // out[tb][c] = relu(b_c + sum_k sum_f Txk[f][tb]*W[k][f][c])
    int tb = t >> 2;
    int c0 = (t & 3) << 3;   // 8 channels per thread
    float y[8];
#pragma unroll
    for (int i = 0; i < 8; i++) y[i] = 0.f;
#pragma unroll
    for (int k = 0; k < 3; k++) {
        const float* xr = sT + k * 512 + tb;       // element f at xr[f*32]
        const float* wk = sW + k * 512;
#pragma unroll
        for (int f = 0; f < FIN; f++) {
            float xv = xr[f * 32];
            const float* wr = wk + f * 32 + c0;
#pragma unroll
            for (int i = 0; i < 8; i++) y[i] += xv * wr[i];
        }
    }
    float* outp = g_cheb + n * 1024 + tb * 32 + c0;
#pragma unroll
    for (int i = 0; i < 8; i++) outp[i] = fmaxf(y[i] + sB[c0 + i], 0.f);
}

// ------- final: time conv + residual + ReLU + LayerNorm + write ---------
// per (b,n) unit: Y(64x8) = A(64x112) * Z(112x8) + bias ; relu ; LN over 64
// GEMM uses packed fma.rn.f32x2 (identical rounding to scalar FFMA chain).
__global__ void k_final(const float* __restrict__ X,
                        const float* __restrict__ timeW, const float* __restrict__ timeB,
                        const float* __restrict__ resW,  const float* __restrict__ resB,
                        const float* __restrict__ gamma, const float* __restrict__ beta,
                        float* __restrict__ out) {
    __shared__ float As[112 * 64];                   // transposed: As[kk*64+co]
    __shared__ __align__(16) float Zs[4][896];       // per-group Z (112x8)
    __shared__ float sBias[64], sG[64], sBt[64];
    __shared__ float redS[4][2][8], redQ[4][2][8];
    int tid = threadIdx.x;

    for (int i = tid; i < 7168; i += 256) {
        int kk = i >> 6, co = i & 63;
        float w;
        if (kk < 96) { int ci = kk / 3, dt = kk - ci * 3; w = timeW[co * 96 + ci * 3 + dt]; }
        else         { w = resW[co * 16 + (kk - 96)]; }
        As[i] = w;
    }
    if (tid < 64) { sBias[tid] = timeB[tid] + resB[tid]; sG[tid] = gamma[tid]; sBt[tid] = beta[tid]; }
    __syncthreads();

    int g = tid >> 6, co = tid & 63;
    int lane = tid & 31, wsub = (tid >> 5) & 1;

    for (int round = 0; round < 8; round++) {
        int unit = blockIdx.x * 32 + round * 4 + g;   // 0..39999
        int b = unit / NN, n = unit - b * NN;

        // build Z: kk<96 -> time-conv patch (ci,dt), kk>=96 -> residual X
        const float* cbase = g_cheb + n * 1024 + b * 256;       // [tau*32+ci]
        const float* xbase = X + (size_t)(b * NN + n) * 128;    // [f*8+t]
        float* Z = Zs[g];
        for (int i = co; i < 896; i += 64) {
            int kk = i >> 3, t = i & 7;
            float v;
            if (kk < 96) {
                int ci = kk / 3, dt = kk - ci * 3;
                int tau = t + dt - 1;
                v = (tau >= 0 && tau < TT) ? cbase[tau * 32 + ci] : 0.f;
            } else {
                v = xbase[(kk - 96) * 8 + t];
            }
            Z[i] = v;
        }
        __syncthreads();

        float bco = sBias[co];
        unsigned long long y01 = pk2(bco, bco);
        unsigned long long y23 = pk2(bco, bco);
        unsigned long long y45 = pk2(bco, bco);
        unsigned long long y67 = pk2(bco, bco);
        const float4* Z4 = reinterpret_cast<const float4*>(Z);
        const float*  Ap = As + co;
#pragma unroll 4
        for (int kk = 0; kk < 112; kk++) {
            float a = Ap[kk * 64];
            unsigned long long aa = pk2(a, a);
            float4 z0 = Z4[kk * 2];
            float4 z1 = Z4[kk * 2 + 1];
            fma2(y01, aa, pk2(z0.x, z0.y));
            fma2(y23, aa, pk2(z0.z, z0.w));
            fma2(y45, aa, pk2(z1.x, z1.y));
            fma2(y67, aa, pk2(z1.z, z1.w));
        }
        float y[8];
        { float2 p = upk2(y01); y[0] = p.x; y[1] = p.y; }
        { float2 p = upk2(y23); y[2] = p.x; y[3] = p.y; }
        { float2 p = upk2(y45); y[4] = p.x; y[5] = p.y; }
        { float2 p = upk2(y67); y[6] = p.x; y[7] = p.y; }
#pragma unroll
        for (int t = 0; t < 8; t++) y[t] = fmaxf(y[t], 0.f);

        // LayerNorm over 64 channels — two-pass (matches jnp.var semantics)
        float s[8];
#pragma unroll
        for (int t = 0; t < 8; t++) s[t] = y[t];
#pragma unroll
        for (int off = 16; off > 0; off >>= 1) {
#pragma unroll
            for (int t = 0; t < 8; t++) s[t] += __shfl_xor_sync(0xffffffffu, s[t], off);
        }
        if (lane == 0) {
#pragma unroll
            for (int t = 0; t < 8; t++) redS[g][wsub][t] = s[t];
        }
        __syncthreads();

        float mu[8], q[8];
#pragma unroll
        for (int t = 0; t < 8; t++) {
            mu[t] = (redS[g][0][t] + redS[g][1][t]) * (1.f / 64.f);
            float d = y[t] - mu[t];
            q[t] = d * d;
        }
#pragma unroll
        for (int off = 16; off > 0; off >>= 1) {
#pragma unroll
            for (int t = 0; t < 8; t++) q[t] += __shfl_xor_sync(0xffffffffu, q[t], off);
        }
        if (lane == 0) {
#pragma unroll
            for (int t = 0; t < 8; t++) redQ[g][wsub][t] = q[t];
        }
        __syncthreads();

        float ov[8];
#pragma unroll
        for (int t = 0; t < 8; t++) {
            float var = (redQ[g][0][t] + redQ[g][1][t]) * (1.f / 64.f);
            float inv = rsqrtf(var + 1e-5f);
            ov[t] = (y[t] - mu[t]) * inv * sG[co] + sBt[co];
        }
        float4* op = reinterpret_cast<float4*>(out + ((size_t)unit * 64 + co) * 8);
        op[0] = make_float4(ov[0], ov[1], ov[2], ov[3]);
        op[1] = make_float4(ov[4], ov[5], ov[6], ov[7]);
    }
}

// ---------------- launch ----------------
extern "C" void kernel_launch(void* const* d_in, const int* in_sizes, int n_in,
                              void* d_out, int out_size) {
    const float* X     = (const float*)d_in[0];
    const int*   ei    = (const int*)  d_in[1];
    const float* chebW = (const float*)d_in[2];
    const float* chebB = (const float*)d_in[3];
    const float* timeW = (const float*)d_in[4];
    const float* timeB = (const float*)d_in[5];
    const float* resW  = (const float*)d_in[6];
    const float* resB  = (const float*)d_in[7];
    const float* gam   = (const float*)d_in[8];
    const float* bet   = (const float*)d_in[9];
    float* out = (float*)d_out;

    int E = in_sizes[1] / 2;
    const int* src = ei;
    const int* dst = ei + E;
    int EB = (E + 255) / 256;

    const int PSMEM = (NN + ECAP) * (int)sizeof(float);   // 136000 B
    static int smem_set = 0;
    if (!smem_set) {
        cudaFuncSetAttribute(k_power, cudaFuncAttributeMaxDynamicSharedMemorySize, PSMEM);
        smem_set = 1;
    }

    k_permute<<<(NN * BB * FIN + 255) / 256, 256>>>(X);       // 1 (+zero)
    k_hist<<<EB, 256>>>(dst, E);                              // 2
    k_scan<<<1, 1024>>>();                                    // 3
    k_power<<<CSZ, 1024, PSMEM>>>(src, dst, E);               // 4  <- profiled
    k_lhat1<<<NN, 128>>>();                                   // 5
    k_lhat2cheb<<<NN, 128>>>(chebW, chebB);                   // 6
    k_final<<<1250, 256>>>(X, timeW, timeB, resW, resB, gam, bet, out);  // 7
}

// round 15
// speedup vs baseline: 1.0916x; 1.0454x over previous
#include <cuda_runtime.h>
#include <stdint.h>

// R15: mega-kernel — power iteration (cluster 0, 8 SMs) runs CONCURRENTLY
// with the lambda-free Y1 = L*Tx0 SpMM (136 worker blocks). lhat chain
// re-expressed via lambda-free Y1/Y2 with scalar recombination.

// Problem constants (fixed shapes)
#define NN   10000       // nodes
#define BB   4           // batch
#define FIN  16          // input features
#define TT   8           // time steps
#define CCH  32          // cheb channels
#define CTM  64          // time channels
#define MAXE 160000      // edges
#define ITERS 64         // power iterations
#define CSZ  8           // cluster size (power cluster)
#define GRID 144         // mega grid (8 power + 136 workers; /8 = 18 clusters)
#define NPC  1250        // nodes per power CTA (NN / CSZ)
#define ECAP 24000       // per-CTA smem edge cache capacity (mean 20000)
#define TOTX (NN*512)    // Tx element count = N * F(16) * TB(32)

// ---------------- scratch (device globals; no allocation) ----------------
__device__ __align__(16) float g_Tx0[TOTX];
__device__ __align__(16) float g_Y1[TOTX];
__device__ __align__(16) float g_cheb[NN*1024];   // [n][tb(32)][c(32)]
__device__ int   g_indeg[NN];
__device__ int   g_rowptr[NN+1];
__device__ int   g_cursor[NN];
__device__ int   g_col[MAXE];
__device__ __align__(16) float g_u0[NN];
__device__ __align__(16) float g_u1[NN];
__device__ float g_lmax;

// ---------------- packed f32x2 helpers (sm_100a) -------------------------
__device__ __forceinline__ unsigned long long pk2(float a, float b) {
    unsigned long long r;
    asm("mov.b64 %0, {%1, %2};" : "=l"(r) : "f"(a), "f"(b));
    return r;
}
__device__ __forceinline__ void fma2(unsigned long long& d, unsigned long long a, unsigned long long b) {
    asm("fma.rn.f32x2 %0, %1, %2, %0;" : "+l"(d) : "l"(a), "l"(b));
}
__device__ __forceinline__ float2 upk2(unsigned long long v) {
    float2 f;
    asm("mov.b64 {%0, %1}, %2;" : "=f"(f.x), "=f"(f.y) : "l"(v));
    return f;
}

// ---------------- permute + zero (launch 1) ------------------------------
__global__ void k_permute(const float* __restrict__ X) {
    int i = blockIdx.x * blockDim.x + threadIdx.x;   // [0, 640000)
    if (i < NN) g_indeg[i] = 0;
    if (i >= NN * BB * FIN) return;
    int f = i / (BB * NN);
    int r = i - f * (BB * NN);
    int b = r / NN;
    int n = r - b * NN;
    const float4* src = reinterpret_cast<const float4*>(X + ((size_t)((b * NN + n) * FIN + f)) * TT);
    float4* dst = reinterpret_cast<float4*>(g_Tx0 + (size_t)i * TT);
    dst[0] = src[0];
    dst[1] = src[1];
}

__global__ void k_hist(const int* __restrict__ dst, int E) {
    int e = blockIdx.x * blockDim.x + threadIdx.x;
    if (e < E) atomicAdd(&g_indeg[dst[e]], 1);
}

__global__ void k_scan() {   // 1 block, 1024 threads
    __shared__ int ps[1024];
    const int CH = 10;       // 1024*10 >= NN
    int t = threadIdx.x;
    int base = t * CH;
    int sum = 0;
#pragma unroll
    for (int i = 0; i < CH; i++) { int idx = base + i; if (idx < NN) sum += g_indeg[idx]; }
    ps[t] = sum; __syncthreads();
    for (int off = 1; off < 1024; off <<= 1) {
        int v = ps[t];
        int a = (t >= off) ? ps[t - off] : 0;
        __syncthreads();
        ps[t] = v + a;
        __syncthreads();
    }
    int run = (t == 0) ? 0 : ps[t - 1];
#pragma unroll
    for (int i = 0; i < CH; i++) {
        int idx = base + i;
        if (idx < NN) { g_rowptr[idx] = run; g_cursor[idx] = run; run += g_indeg[idx]; }
    }
    if (t == 1023) g_rowptr[NN] = ps[1023];
}

__global__ void k_fill(const int* __restrict__ src, const int* __restrict__ dst, int E) {
    int e = blockIdx.x * blockDim.x + threadIdx.x;
    if (e < E) {
        int p = atomicAdd(&g_cursor[dst[e]], 1);
        g_col[p] = src[e];
    }
}

// ---------------- mega: power iteration || Y1 SpMM -----------------------
// Blocks 0..7 (cluster 0): R14-validated power iteration (per-CTA local
// norm from staged vector, HW cluster barriers, smem edge cache). Vector-
// element arithmetic byte-identical to R13/R14:
//   iter 1: w = fl(deg*C0) - chain_deg(C0)   (null-space rounding residue)
//   iter k: acc = (deg*cur[n] - sum cur[col]) * (1/sqrt(S[k-1]))
// Blocks 8..143 (other clusters, no cluster-barrier use): Y1 = L*Tx0,
// i.e. Y1[n] = deg_n*Tx0[n] - sum_{s in in(n)} Tx0[s]  (512 floats/node).
__global__ void __cluster_dims__(CSZ, 1, 1) __launch_bounds__(1024, 1)
k_mega() {
    extern __shared__ __align__(16) float dyn[];   // power: [NN] vec + [ECAP] edges
    __shared__ float red[33];
    int tid = threadIdx.x;

    if (blockIdx.x < CSZ) {
        // ================= POWER ROLE =================
        float* sm = dyn;
        int*   se = reinterpret_cast<int*>(dyn + NN);
        int rank = blockIdx.x;               // cluster 0: rank == blockIdx.x
        int lane = tid & 31, warp = tid >> 5;
        const float C0 = 0.01f;              // 1/sqrt(10000) rounded to f32

        int base  = rank * NPC;
        int ebase = g_rowptr[base];
        int ecnt  = g_rowptr[base + NPC] - ebase;
        bool fastE = (ecnt <= ECAP);
        for (int i = tid; i < ecnt && i < ECAP; i += 1024)
            se[i] = __ldcg(&g_col[ebase + i]);

        int n0 = base + tid;
        int n1 = base + 1024 + tid;
        bool v1 = (tid < NPC - 1024);        // tid < 226
        int l00 = g_rowptr[n0] - ebase;
        int m0  = g_rowptr[n0 + 1] - (l00 + ebase);
        int l01 = 0, m1 = 0;
        if (v1) { l01 = g_rowptr[n1] - ebase; m1 = g_rowptr[n1 + 1] - (l01 + ebase); }
        float deg0 = (float)m0, deg1 = (float)m1;
        __syncthreads();

        float* cur = g_u0;
        float* nxt = g_u1;
        for (int k = 1; k <= ITERS; k++) {
            if (k == 1) {
                {
                    float av = 0.0f;
                    for (int j = 0; j < m0; j++) av = __fadd_rn(av, C0);
                    float w = __fsub_rn(__fmul_rn(deg0, C0), av);
                    nxt[n0] = w;
                }
                if (v1) {
                    float av = 0.0f;
                    for (int j = 0; j < m1; j++) av = __fadd_rn(av, C0);
                    float w = __fsub_rn(__fmul_rn(deg1, C0), av);
                    nxt[n1] = w;
                }
            } else {
                const float4* c4 = reinterpret_cast<const float4*>(cur);
                float4* s4 = reinterpret_cast<float4*>(sm);
                float ss = 0.0f;
                for (int i = tid; i < NN / 4; i += 1024) {
                    float4 f = __ldcg(c4 + i);
                    s4[i] = f;
                    ss += f.x * f.x + f.y * f.y + f.z * f.z + f.w * f.w;
                }
#pragma unroll
                for (int off = 16; off > 0; off >>= 1)
                    ss += __shfl_xor_sync(0xffffffffu, ss, off);
                if (lane == 0) red[warp] = ss;
                __syncthreads();
                if (warp == 0) {
                    float v = red[lane];
#pragma unroll
                    for (int off = 16; off > 0; off >>= 1)
                        v += __shfl_xor_sync(0xffffffffu, v, off);
                    if (lane == 0) red[32] = v;
                }
                __syncthreads();
                float inv = 1.0f / sqrtf(red[32]);

                {
                    float acc = deg0 * sm[n0];
                    if (fastE) {
#pragma unroll 4
                        for (int j = 0; j < m0; j++) acc -= sm[se[l00 + j]];
                    } else {
                        for (int j = 0; j < m0; j++) acc -= sm[__ldcg(&g_col[ebase + l00 + j])];
                    }
                    acc *= inv;
                    nxt[n0] = acc;
                }
                if (v1) {
                    float acc = deg1 * sm[n1];
                    if (fastE) {
#pragma unroll 4
                        for (int j = 0; j < m1; j++) acc -= sm[se[l01 + j]];
                    } else {
                        for (int j = 0; j < m1; j++) acc -= sm[__ldcg(&g_col[ebase + l01 + j])];
                    }
                    acc *= inv;
                    nxt[n1] = acc;
                }
            }
            __threadfence();
            asm volatile("barrier.cluster.arrive.aligned;" ::: "memory");
            asm volatile("barrier.cluster.wait.aligned;" ::: "memory");
            float* tmp = cur; cur = nxt; nxt = tmp;
        }

        // final norm ||u_64|| -> lambda_max
        {
            const float4* c4 = reinterpret_cast<const float4*>(cur);
            float ss = 0.0f;
            for (int i = tid; i < NN / 4; i += 1024) {
                float4 f = __ldcg(c4 + i);
                ss += f.x * f.x + f.y * f.y + f.z * f.z + f.w * f.w;
            }
#pragma unroll
            for (int off = 16; off > 0; off >>= 1)
                ss += __shfl_xor_sync(0xffffffffu, ss, off);
            if (lane == 0) red[warp] = ss;
            __syncthreads();
            if (warp == 0) {
                float v = red[lane];
#pragma unroll
                for (int off = 16; off > 0; off >>= 1)
                    v += __shfl_xor_sync(0xffffffffu, v, off);
                if (lane == 0) red[32] = v;
            }
            __syncthreads();
            if (rank == 0 && tid == 0) g_lmax = sqrtf(red[32]);
        }
    } else {
        // ================= Y1 ROLE =================
        int t   = tid & 127;                 // float4 lane within node row
        int sub = tid >> 7;                  // 0..7 node sub-slot
        const float4* x0 = reinterpret_cast<const float4*>(g_Tx0);
        float4* y1 = reinterpret_cast<float4*>(g_Y1);
        const int stride = (GRID - CSZ) * 8;
        for (int n = (blockIdx.x - CSZ) * 8 + sub; n < NN; n += stride) {
            int e0 = g_rowptr[n], e1 = g_rowptr[n + 1];
            float4 acc = make_float4(0.f, 0.f, 0.f, 0.f);
            for (int j = e0; j < e1; j++) {
                int s = g_col[j];
                float4 v = x0[s * 128 + t];
                acc.x += v.x; acc.y += v.y; acc.z += v.z; acc.w += v.w;
            }
            float degf = (float)(e1 - e0);
            float4 xx = x0[n * 128 + t];
            float4 o;
            o.x = degf * xx.x - acc.x;
            o.y = degf * xx.y - acc.y;
            o.z = degf * xx.z - acc.z;
            o.w = degf * xx.w - acc.w;
            y1[n * 128 + t] = o;
        }
    }
}

// ------- chebY2: Y2 = L*Y1 gather + Tx recombination + Cheb GEMM --------
// Tx1 = a*Y1 - Tx0 ; L(Tx1) = a*Y2 - Y1 ; Tx2 = 2*(a*L(Tx1) - Tx1) - Tx0
// with a = 2/lambda. Rows f-major: element (f2, tb) at index f2*32 + tb.
__global__ void k_chebY2(const float* __restrict__ chebW, const float* __restrict__ chebB) {
    __shared__ __align__(16) float sT[1536];   // Tx0,Tx1,Tx2 rows of this node
    __shared__ float sW[1536];                 // cheb_W (3,16,32)
    __shared__ float sB[CCH];
    int n = blockIdx.x;
    int t = threadIdx.x;   // 128 threads
    for (int i = t; i < 1536; i += 128) sW[i] = chebW[i];
    if (t < CCH) sB[t] = chebB[t];

    const float4* x0 = reinterpret_cast<const float4*>(g_Tx0);
    const float4* y1 = reinterpret_cast<const float4*>(g_Y1);
    float4 acc = make_float4(0.f, 0.f, 0.f, 0.f);
    int e0 = g_rowptr[n], e1 = g_rowptr[n + 1];
    for (int j = e0; j < e1; j++) {
        int s = g_col[j];
        float4 v = y1[s * 128 + t];
        acc.x += v.x; acc.y += v.y; acc.z += v.z; acc.w += v.w;
    }
    float degf = (float)(e1 - e0);
    float a = 2.0f / g_lmax;
    float4 y1n = y1[n * 128 + t];
    float4 t0v = x0[n * 128 + t];
    float4 y2, t1v, t2v;
    y2.x = degf * y1n.x - acc.x;
    y2.y = degf * y1n.y - acc.y;
    y2.z = degf * y1n.z - acc.z;
    y2.w = degf * y1n.w - acc.w;
    t1v.x = a * y1n.x - t0v.x;
    t1v.y = a * y1n.y - t0v.y;
    t1v.z = a * y1n.z - t0v.z;
    t1v.w = a * y1n.w - t0v.w;
    // L(Tx1) = a*Y2 - Y1 ; Tx2 = 2*(a*L(Tx1) - Tx1) - Tx0
    t2v.x = 2.f * (a * (a * y2.x - y1n.x) - t1v.x) - t0v.x;
    t2v.y = 2.f * (a * (a * y2.y - y1n.y) - t1v.y) - t0v.y;
    t2v.z = 2.f * (a * (a * y2.z - y1n.z) - t1v.z) - t0v.z;
    t2v.w = 2.f * (a * (a * y2.w - y1n.w) - t1v.w) - t0v.w;
    reinterpret_cast<float4*>(sT)[t]       = t0v;   // Tx0 row (f-major)
    reinterpret_cast<float4*>(sT)[128 + t] = t1v;   // Tx1 row
    reinterpret_cast<float4*>(sT)[256 + t] = t2v;   // Tx2 row
    __syncthreads();

    // out[tb][c] = relu(b_c + sum_k sum_f Txk[f][tb]*W[k][f][c])
    int tb = t >> 2;
    int c0 = (t & 3) << 3;   // 8 channels per thread
    float y[8];
#pragma unroll
    for (int i = 0; i < 8; i++) y[i] = 0.f;
#pragma unroll
    for (int k = 0; k < 3; k++) {
        const float* xr = sT + k * 512 + tb;       // element f at xr[f*32]
        const float* wk = sW + k * 512;
#pragma unroll
        for (int f = 0; f < FIN; f++) {
            float xv = xr[f * 32];
            const float* wr = wk + f * 32 + c0;
#pragma unroll
            for (int i = 0; i < 8; i++) y[i] += xv * wr[i];
        }
    }
    float* outp = g_cheb + n * 1024 + tb * 32 + c0;
#pragma unroll
    for (int i = 0; i < 8; i++) outp[i] = fmaxf(y[i] + sB[c0 + i], 0.f);
}

// ------- final: time conv + residual + ReLU + LayerNorm + write ---------
__global__ void k_final(const float* __restrict__ X,
                        const float* __restrict__ timeW, const float* __restrict__ timeB,
                        const float* __restrict__ resW,  const float* __restrict__ resB,
                        const float* __restrict__ gamma, const float* __restrict__ beta,
                        float* __restrict__ out) {
    __shared__ float As[112 * 64];                   // transposed: As[kk*64+co]
    __shared__ __align__(16) float Zs[4][896];       // per-group Z (112x8)
    __shared__ float sBias[64], sG[64], sBt[64];
    __shared__ float redS[4][2][8], redQ[4][2][8];
    int tid = threadIdx.x;

    for (int i = tid; i < 7168; i += 256) {
        int kk = i >> 6, co = i & 63;
        float w;
        if (kk < 96) { int ci = kk / 3, dt = kk - ci * 3; w = timeW[co * 96 + ci * 3 + dt]; }
        else         { w = resW[co * 16 + (kk - 96)]; }
        As[i] = w;
    }
    if (tid < 64) { sBias[tid] = timeB[tid] + resB[tid]; sG[tid] = gamma[tid]; sBt[tid] = beta[tid]; }
    __syncthreads();

    int g = tid >> 6, co = tid & 63;
    int lane = tid & 31, wsub = (tid >> 5) & 1;

    for (int round = 0; round < 8; round++) {
        int unit = blockIdx.x * 32 + round * 4 + g;   // 0..39999
        int b = unit / NN, n = unit - b * NN;

        const float* cbase = g_cheb + n * 1024 + b * 256;       // [tau*32+ci]
        const float* xbase = X + (size_t)(b * NN + n) * 128;    // [f*8+t]
        float* Z = Zs[g];
        for (int i = co; i < 896; i += 64) {
            int kk = i >> 3, t = i & 7;
            float v;
            if (kk < 96) {
                int ci = kk / 3, dt = kk - ci * 3;
                int tau = t + dt - 1;
                v = (tau >= 0 && tau < TT) ? cbase[tau * 32 + ci] : 0.f;
            } else {
                v = xbase[(kk - 96) * 8 + t];
            }
            Z[i] = v;
        }
        __syncthreads();

        float bco = sBias[co];
        unsigned long long y01 = pk2(bco, bco);
        unsigned long long y23 = pk2(bco, bco);
        unsigned long long y45 = pk2(bco, bco);
        unsigned long long y67 = pk2(bco, bco);
        const float4* Z4 = reinterpret_cast<const float4*>(Z);
        const float*  Ap = As + co;
#pragma unroll 4
        for (int kk = 0; kk < 112; kk++) {
            float a = Ap[kk * 64];
            unsigned long long aa = pk2(a, a);
            float4 z0 = Z4[kk * 2];
            float4 z1 = Z4[kk * 2 + 1];
            fma2(y01, aa, pk2(z0.x, z0.y));
            fma2(y23, aa, pk2(z0.z, z0.w));
            fma2(y45, aa, pk2(z1.x, z1.y));
            fma2(y67, aa, pk2(z1.z, z1.w));
        }
        float y[8];
        { float2 p = upk2(y01); y[0] = p.x; y[1] = p.y; }
        { float2 p = upk2(y23); y[2] = p.x; y[3] = p.y; }
        { float2 p = upk2(y45); y[4] = p.x; y[5] = p.y; }
        { float2 p = upk2(y67); y[6] = p.x; y[7] = p.y; }
#pragma unroll
        for (int t = 0; t < 8; t++) y[t] = fmaxf(y[t], 0.f);

        // LayerNorm over 64 channels — two-pass (matches jnp.var semantics)
        float s[8];
#pragma unroll
        for (int t = 0; t < 8; t++) s[t] = y[t];
#pragma unroll
        for (int off = 16; off > 0; off >>= 1) {
#pragma unroll
            for (int t = 0; t < 8; t++) s[t] += __shfl_xor_sync(0xffffffffu, s[t], off);
        }
        if (lane == 0) {
#pragma unroll
            for (int t = 0; t < 8; t++) redS[g][wsub][t] = s[t];
        }
        __syncthreads();

        float mu[8], q[8];
#pragma unroll
        for (int t = 0; t < 8; t++) {
            mu[t] = (redS[g][0][t] + redS[g][1][t]) * (1.f / 64.f);
            float d = y[t] - mu[t];
            q[t] = d * d;
        }
#pragma unroll
        for (int off = 16; off > 0; off >>= 1) {
#pragma unroll
            for (int t = 0; t < 8; t++) q[t] += __shfl_xor_sync(0xffffffffu, q[t], off);
        }
        if (lane == 0) {
#pragma unroll
            for (int t = 0; t < 8; t++) redQ[g][wsub][t] = q[t];
        }
        __syncthreads();

        float ov[8];
#pragma unroll
        for (int t = 0; t < 8; t++) {
            float var = (redQ[g][0][t] + redQ[g][1][t]) * (1.f / 64.f);
            float inv = rsqrtf(var + 1e-5f);
            ov[t] = (y[t] - mu[t]) * inv * sG[co] + sBt[co];
        }
        float4* op = reinterpret_cast<float4*>(out + ((size_t)unit * 64 + co) * 8);
        op[0] = make_float4(ov[0], ov[1], ov[2], ov[3]);
        op[1] = make_float4(ov[4], ov[5], ov[6], ov[7]);
    }
}

// ---------------- launch ----------------
extern "C" void kernel_launch(void* const* d_in, const int* in_sizes, int n_in,
                              void* d_out, int out_size) {
    const float* X     = (const float*)d_in[0];
    const int*   ei    = (const int*)  d_in[1];
    const float* chebW = (const float*)d_in[2];
    const float* chebB = (const float*)d_in[3];
    const float* timeW = (const float*)d_in[4];
    const float* timeB = (const float*)d_in[5];
    const float* resW  = (const float*)d_in[6];
    const float* resB  = (const float*)d_in[7];
    const float* gam   = (const float*)d_in[8];
    const float* bet   = (const float*)d_in[9];
    float* out = (float*)d_out;

    int E = in_sizes[1] / 2;
    const int* src = ei;
    const int* dst = ei + E;
    int EB = (E + 255) / 256;

    const int PSMEM = (NN + ECAP) * (int)sizeof(float);   // 136000 B
    static int smem_set = 0;
    if (!smem_set) {
        cudaFuncSetAttribute(k_mega, cudaFuncAttributeMaxDynamicSharedMemorySize, PSMEM);
        smem_set = 1;
    }

    k_permute<<<(NN * BB * FIN + 255) / 256, 256>>>(X);       // 1 (+zero)
    k_hist<<<EB, 256>>>(dst, E);                              // 2
    k_scan<<<1, 1024>>>();                                    // 3
    k_fill<<<EB, 256>>>(src, dst, E);                         // 4
    k_mega<<<GRID, 1024, PSMEM>>>();                          // 5 power || Y1
    k_chebY2<<<NN, 128>>>(chebW, chebB);                      // 6
    k_final<<<1250, 256>>>(X, timeW, timeB, resW, resB, gam, bet, out);  // 7
}